// round 14
// baseline (speedup 1.0000x reference)
#include <cuda_runtime.h>
#include <cuda_bf16.h>
#include <stdint.h>

#define NPG  39
#define FDIM 3280
#define BGR  4096
#define MAXE (NPG * 9)

// Frow offsets (concat order)
#define OFF_RES1 39
#define OFF_RES2 351
#define OFF_RES3 2847
#define OFF_OUT0 3198
#define OFF_OUT1 3199
#define OFF_OUT2 3207
#define OFF_OUT3 3271

// GEMM1: K=3280, K'=9840 -> 9856 (154*64). N-tile 96 -> N1PAD 5184 (54*96)
// GEMM2: K=5000, K'=15000 -> 15040 (235*64). N-tile 128.
#define K1SEC 3280
#define K1TT  9856
#define K2SEC 5000
#define K2TT  15040
#define N1PAD 5184

__device__ float g_H[(size_t)BGR * 1024];
__device__ __align__(128) __nv_bfloat16 g_A1[(size_t)BGR * K1TT];
__device__ __align__(128) __nv_bfloat16 g_B1[(size_t)N1PAD * K1TT];
__device__ __align__(128) __nv_bfloat16 g_A2[(size_t)BGR * K2TT];
__device__ __align__(128) __nv_bfloat16 g_B2[(size_t)1024 * K2TT];
__device__ int g_is64;

__device__ __forceinline__ uint32_t smem_u32(const void* p) {
    uint32_t a;
    asm("{ .reg .u64 t; cvta.to.shared.u64 t, %1; cvt.u32.u64 %0, t; }"
        : "=r"(a) : "l"(p));
    return a;
}

__global__ void k_sniff(const int* __restrict__ ei) {
    if (threadIdx.x == 0) g_is64 = (ei[8] == 0) ? 1 : 0;
}

// ===================== fused GAT layer (device) =====================
template <int FIN, int FOUT>
__device__ __forceinline__ void gat_layer(
    int t,
    const float* __restrict__ xin,
    const float* __restrict__ W, const float* __restrict__ as_,
    const float* __restrict__ ad_, const float* __restrict__ bias,
    float* __restrict__ out, float* __restrict__ maxout,
    float* __restrict__ sh, float* __restrict__ sW,
    float* __restrict__ sas, float* __restrict__ sad, float* __restrict__ sb,
    float* __restrict__ ss, float* __restrict__ sd, float* __restrict__ sden,
    float* __restrict__ sew, const short* __restrict__ sse,
    const int* __restrict__ cnt)
{
    for (int i = t; i < FIN * FOUT; i += 256) sW[i] = W[i];
    if (t < FOUT) { sas[t] = as_[t]; sad[t] = ad_[t]; sb[t] = bias[t]; }
    __syncthreads();

    if (FOUT % 4 == 0) {
        constexpr int F4 = FOUT / 4;
        for (int idx = t; idx < NPG * F4; idx += 256) {
            int i = idx / F4, f4 = idx - i * F4;
            float4 a = make_float4(0.f, 0.f, 0.f, 0.f);
            #pragma unroll
            for (int k = 0; k < FIN; k++) {
                float xv = xin[i * FIN + k];
                float4 wv = *(const float4*)&sW[k * FOUT + f4 * 4];
                a.x += xv * wv.x; a.y += xv * wv.y;
                a.z += xv * wv.z; a.w += xv * wv.w;
            }
            *(float4*)&sh[i * FOUT + f4 * 4] = a;
        }
    } else {
        for (int idx = t; idx < NPG * FOUT; idx += 256) {
            int i = idx / FOUT, f = idx - i * FOUT;
            float a = 0.f;
            #pragma unroll 8
            for (int k = 0; k < FIN; k++) a += xin[i * FIN + k] * sW[k * FOUT + f];
            sh[idx] = a;
        }
    }
    __syncthreads();

    for (int i = t; i < NPG; i += 256) {
        float a = 0.f, b = 0.f;
        #pragma unroll
        for (int f = 0; f < FOUT; f++) {
            a += sh[i * FOUT + f] * sas[f];
            b += sh[i * FOUT + f] * sad[f];
        }
        ss[i] = a; sd[i] = b;
    }
    __syncthreads();

    // segment softmax in sorted domain
    for (int i = t; i < NPG; i += 256) {
        int e0 = cnt[i], e1 = cnt[i + 1];
        float di = sd[i];
        float mx = -1e30f;
        for (int p = e0; p < e1; p++) {
            float sc = ss[sse[p]] + di;
            sc = sc > 0.f ? sc : 0.2f * sc;
            sew[p] = sc;
            mx = fmaxf(mx, sc);
        }
        float s = 0.f;
        for (int p = e0; p < e1; p++) {
            float w = __expf(sew[p] - mx);
            sew[p] = w;
            s += w;
        }
        sden[i] = s;
    }
    __syncthreads();

    if (FOUT % 4 == 0) {
        constexpr int F4 = FOUT / 4;
        for (int idx = t; idx < NPG * F4; idx += 256) {
            int i = idx / F4, f4 = idx - i * F4;
            float4 a = make_float4(0.f, 0.f, 0.f, 0.f);
            int e0 = cnt[i], e1 = cnt[i + 1];
            for (int p = e0; p < e1; p++) {
                float w = sew[p];
                float4 hv = *(const float4*)&sh[(int)sse[p] * FOUT + f4 * 4];
                a.x += w * hv.x; a.y += w * hv.y;
                a.z += w * hv.z; a.w += w * hv.w;
            }
            float inv = 1.f / (sden[i] + 1e-16f);
            int base = i * FOUT + f4 * 4;
            out[base + 0] = fmaxf(a.x * inv + sb[f4 * 4 + 0], 0.f);
            out[base + 1] = fmaxf(a.y * inv + sb[f4 * 4 + 1], 0.f);
            out[base + 2] = fmaxf(a.z * inv + sb[f4 * 4 + 2], 0.f);
            out[base + 3] = fmaxf(a.w * inv + sb[f4 * 4 + 3], 0.f);
        }
    } else {
        for (int idx = t; idx < NPG * FOUT; idx += 256) {
            int i = idx / FOUT, f = idx - i * FOUT;
            float a = 0.f;
            int e0 = cnt[i], e1 = cnt[i + 1];
            for (int p = e0; p < e1; p++)
                a += sew[p] * sh[(int)sse[p] * FOUT + f];
            out[idx] = fmaxf(a / (sden[i] + 1e-16f) + sb[f], 0.f);
        }
    }
    __syncthreads();

    for (int f = t; f < FOUT; f += 256) {
        float mv = out[f];
        for (int i = 1; i < NPG; i++) mv = fmaxf(mv, out[i * FOUT + f]);
        maxout[f] = mv;
    }
    __syncthreads();
}

// ===================== fused GAT kernel (4 CTAs/SM) =====================
__global__ __launch_bounds__(256, 4) void k_fgat(
    const float* __restrict__ x, const void* __restrict__ edges,
    int E, int EPG,
    const float* __restrict__ W1, const float* __restrict__ a1s,
    const float* __restrict__ a1d, const float* __restrict__ b1,
    const float* __restrict__ W2, const float* __restrict__ a2s,
    const float* __restrict__ a2d, const float* __restrict__ b2,
    const float* __restrict__ W3, const float* __restrict__ a3s,
    const float* __restrict__ a3d, const float* __restrict__ b3,
    __nv_bfloat16* __restrict__ A1)
{
    __shared__ __align__(16) float Frow[FDIM];
    __shared__ __align__(16) float sh[NPG * 64];
    __shared__ __align__(16) float sW[64 * 9];
    __shared__ float sas[64], sad[64], sb[64];
    __shared__ float ss[NPG], sd[NPG], sden[NPG];
    __shared__ float sew[MAXE];
    __shared__ short elsA[MAXE], eldA[MAXE], sse[MAXE];
    __shared__ int cnt[NPG + 1], off[NPG];

    int g = blockIdx.x;
    int t = threadIdx.x;
    int nE = EPG + NPG;

    if (t < NPG) Frow[t] = x[g * NPG + t];
    if (t < NPG + 1) cnt[t] = 0;
    __syncthreads();

    bool is64 = (g_is64 != 0);
    long long node0 = (long long)g * NPG;
    for (int e = t; e < nE; e += 256) {
        int ls, ld;
        if (e < EPG) {
            long long ge = (long long)g * EPG + e;
            long long sv, dv;
            if (is64) {
                const long long* p = (const long long*)edges;
                sv = p[ge]; dv = p[ge + E];
            } else {
                const int* p = (const int*)edges;
                sv = p[ge]; dv = p[ge + E];
            }
            ls = (int)(sv - node0);
            ld = (int)(dv - node0);
        } else {
            ls = ld = e - EPG;
        }
        elsA[e] = (short)ls; eldA[e] = (short)ld;
        atomicAdd(&cnt[ld], 1);
    }
    __syncthreads();

    if (t == 0) {
        int s = 0;
        for (int i = 0; i < NPG; i++) {
            int c = cnt[i];
            cnt[i] = s; off[i] = s;
            s += c;
        }
        cnt[NPG] = s;
    }
    __syncthreads();

    for (int e = t; e < nE; e += 256) {
        int pos = atomicAdd(&off[eldA[e]], 1);
        sse[pos] = elsA[e];
    }
    if (t == 32) {
        float mv = Frow[0];
        for (int i = 1; i < NPG; i++) mv = fmaxf(mv, Frow[i]);
        Frow[OFF_OUT0] = mv;
    }
    __syncthreads();

    gat_layer<1, 8>(t, &Frow[0], W1, a1s, a1d, b1,
                    &Frow[OFF_RES1], &Frow[OFF_OUT1],
                    sh, sW, sas, sad, sb, ss, sd, sden, sew, sse, cnt);
    gat_layer<8, 64>(t, &Frow[OFF_RES1], W2, a2s, a2d, b2,
                     &Frow[OFF_RES2], &Frow[OFF_OUT2],
                     sh, sW, sas, sad, sb, ss, sd, sden, sew, sse, cnt);
    gat_layer<64, 9>(t, &Frow[OFF_RES2], W3, a3s, a3d, b3,
                     &Frow[OFF_RES3], &Frow[OFF_OUT3],
                     sh, sW, sas, sad, sb, ss, sd, sden, sew, sse, cnt);

    __nv_bfloat16* row = A1 + (size_t)g * K1TT;
    for (int k = t; k < FDIM; k += 256) {
        float v = Frow[k];
        __nv_bfloat16 hi = __float2bfloat16(v);
        __nv_bfloat16 lo = __float2bfloat16(v - __bfloat162float(hi));
        row[k] = hi;
        row[K1SEC + k] = hi;
        row[2 * K1SEC + k] = lo;
    }
}

// ===================== weight split ([hi | lo | hi], stride KtT) ==========
__global__ void k_splitB(const float* __restrict__ W, __nv_bfloat16* __restrict__ Bt,
                         int K, int N, int KtT)
{
    __shared__ float tile[32][33];
    int kb = blockIdx.y * 32, nb = blockIdx.x * 32;
    int tx = threadIdx.x, ty = threadIdx.y;
    for (int r = ty; r < 32; r += 8) {
        int k = kb + r, n = nb + tx;
        tile[r][tx] = (k < K && n < N) ? W[(size_t)k * N + n] : 0.f;
    }
    __syncthreads();
    for (int r = ty; r < 32; r += 8) {
        int n = nb + r, k = kb + tx;
        if (n < N && k < K) {
            float v = tile[tx][r];
            __nv_bfloat16 hi = __float2bfloat16(v);
            __nv_bfloat16 lo = __float2bfloat16(v - __bfloat162float(hi));
            __nv_bfloat16* row = Bt + (size_t)n * KtT;
            row[k] = hi;
            row[K + k] = lo;
            row[2 * K + k] = hi;
        }
    }
}

// ===================== mma.sync GEMM, templated N-tile =====================
// CTA tile 128 x (32*NB16), 4 warps (2x2), warp tile 64 x (16*NB16), BK=64,
// 3 stages, 2 CTAs/SM.
#define ROWB 144

__device__ __forceinline__ void ldm4(uint32_t* r, uint32_t addr) {
    asm volatile("ldmatrix.sync.aligned.m8n8.x4.shared.b16 {%0,%1,%2,%3}, [%4];"
        : "=r"(r[0]), "=r"(r[1]), "=r"(r[2]), "=r"(r[3]) : "r"(addr));
}
__device__ __forceinline__ void mma16816(float* c, const uint32_t* a,
                                         uint32_t b0, uint32_t b1) {
    asm volatile("mma.sync.aligned.m16n8k16.row.col.f32.bf16.bf16.f32 "
        "{%0,%1,%2,%3}, {%4,%5,%6,%7}, {%8,%9}, {%0,%1,%2,%3};"
        : "+f"(c[0]), "+f"(c[1]), "+f"(c[2]), "+f"(c[3])
        : "r"(a[0]), "r"(a[1]), "r"(a[2]), "r"(a[3]), "r"(b0), "r"(b1));
}

__device__ __forceinline__ void wsplit2(__nv_bfloat16* base, int r, int KsT,
                                        int KSec, int col, float v0, float v1) {
    __nv_bfloat16 h0 = __float2bfloat16(v0);
    __nv_bfloat16 h1 = __float2bfloat16(v1);
    __nv_bfloat162 lo2 = __floats2bfloat162_rn(v0 - __bfloat162float(h0),
                                               v1 - __bfloat162float(h1));
    uint32_t hp; { __nv_bfloat162 hh; hh.x = h0; hh.y = h1; hp = *(uint32_t*)&hh; }
    uint32_t lp = *(uint32_t*)&lo2;
    __nv_bfloat16* row = base + (size_t)r * KsT;
    *(uint32_t*)(row + col) = hp;
    *(uint32_t*)(row + KSec + col) = hp;
    *(uint32_t*)(row + 2 * KSec + col) = lp;
}

template <int EPI, int NB16>
__global__ __launch_bounds__(128, 2) void k_mma(
    const __nv_bfloat16* __restrict__ A, const __nv_bfloat16* __restrict__ B,
    const float* __restrict__ bias, float* __restrict__ C,
    __nv_bfloat16* __restrict__ Csp, int KsT, int KSec,
    int Kt, int steps, int Nreal)
{
    constexpr int NTILE = 32 * NB16;        // CTA N-tile (128 or 96)
    constexpr int A_STG = 128 * ROWB;
    constexpr int B_STG = NTILE * ROWB;
    constexpr int STG = A_STG + B_STG;

    extern __shared__ char smem[];
    uint32_t sb = smem_u32(smem);
    int tid = threadIdx.x;
    int lane = tid & 31, wid = tid >> 5;
    int wm = wid & 1, wn = wid >> 1;
    int bm = blockIdx.y * 128, bn = blockIdx.x * NTILE;

    const char* Abase = (const char*)A + (size_t)bm * Kt * 2;
    const char* Bbase = (const char*)B + (size_t)bn * Kt * 2;
    size_t gsA = (size_t)Kt * 2;

    auto load_stage = [&](int s, int slot) {
        size_t kb = (size_t)s * 128;
        uint32_t base = sb + slot * STG;
        #pragma unroll
        for (int i = 0; i < 8; i++) {
            int c = tid + i * 128;
            int row = c >> 3, kc = c & 7;
            uint32_t dst = base + row * ROWB + kc * 16;
            const char* src = Abase + (size_t)row * gsA + kb + kc * 16;
            asm volatile("cp.async.cg.shared.global [%0], [%1], 16;"
                         :: "r"(dst), "l"(src));
        }
        #pragma unroll
        for (int i = 0; i < 2 * NB16; i++) {
            int c = tid + i * 128;
            int row = c >> 3, kc = c & 7;
            uint32_t dst = base + A_STG + row * ROWB + kc * 16;
            const char* src = Bbase + (size_t)row * gsA + kb + kc * 16;
            asm volatile("cp.async.cg.shared.global [%0], [%1], 16;"
                         :: "r"(dst), "l"(src));
        }
    };

    float acc[4][2 * NB16][4];
    #pragma unroll
    for (int i = 0; i < 4; i++)
        #pragma unroll
        for (int j = 0; j < 2 * NB16; j++)
            #pragma unroll
            for (int q = 0; q < 4; q++) acc[i][j][q] = 0.f;

    load_stage(0, 0);
    asm volatile("cp.async.commit_group;" ::: "memory");
    load_stage(1, 1);
    asm volatile("cp.async.commit_group;" ::: "memory");

    int lr = lane & 15;
    int lc = (lane >> 4) * 16;

    for (int j = 0; j < steps; j++) {
        asm volatile("cp.async.wait_group 1;" ::: "memory");
        __syncthreads();

        if (j + 2 < steps) load_stage(j + 2, (j + 2) % 3);
        asm volatile("cp.async.commit_group;" ::: "memory");

        uint32_t sA = sb + (j % 3) * STG;
        uint32_t sB = sA + A_STG;
        uint32_t aA = sA + (wm * 64 + lr) * ROWB + lc;
        uint32_t aB = sB + (wn * (16 * NB16) + lr) * ROWB + lc;

        #pragma unroll
        for (int ks = 0; ks < 4; ks++) {
            uint32_t a[4][4], b[NB16][4];
            #pragma unroll
            for (int mi = 0; mi < 4; mi++)
                ldm4(a[mi], aA + mi * 16 * ROWB + ks * 32);
            #pragma unroll
            for (int ng = 0; ng < NB16; ng++)
                ldm4(b[ng], aB + ng * 16 * ROWB + ks * 32);
            #pragma unroll
            for (int mi = 0; mi < 4; mi++)
                #pragma unroll
                for (int ng = 0; ng < NB16; ng++) {
                    mma16816(acc[mi][2 * ng],     a[mi], b[ng][0], b[ng][2]);
                    mma16816(acc[mi][2 * ng + 1], a[mi], b[ng][1], b[ng][3]);
                }
        }
    }

    int r0base = bm + wm * 64 + (lane >> 2);
    int c0base = bn + wn * (16 * NB16) + (lane & 3) * 2;
    #pragma unroll
    for (int mi = 0; mi < 4; mi++) {
        #pragma unroll
        for (int ni = 0; ni < 2 * NB16; ni++) {
            int col = c0base + ni * 8;
            if (col >= Nreal) continue;   // col even, Nreal even -> pair safe
            float bv0 = __ldg(&bias[col]);
            float bv1 = __ldg(&bias[col + 1]);
            int r0 = r0base + mi * 16;
            int r1 = r0 + 8;
            float v0 = fmaxf(acc[mi][ni][0] + bv0, 0.f);
            float v1 = fmaxf(acc[mi][ni][1] + bv1, 0.f);
            float v2 = fmaxf(acc[mi][ni][2] + bv0, 0.f);
            float v3 = fmaxf(acc[mi][ni][3] + bv1, 0.f);
            if (EPI == 0) {
                *(float2*)(C + (size_t)r0 * Nreal + col) = make_float2(v0, v1);
                *(float2*)(C + (size_t)r1 * Nreal + col) = make_float2(v2, v3);
            } else {
                wsplit2(Csp, r0, KsT, KSec, col, v0, v1);
                wsplit2(Csp, r1, KsT, KSec, col, v2, v3);
            }
        }
    }
}

#define SMEM_NB3 (3 * (128 * ROWB + 96 * ROWB))    // 96768
#define SMEM_NB4 (3 * (128 * ROWB + 128 * ROWB))   // 110592

// ===================== final skinny layer =====================
__global__ __launch_bounds__(256) void k_lin3(
    const float* __restrict__ H, const float* __restrict__ W,
    const float* __restrict__ b, float* __restrict__ out)
{
    __shared__ float Wt[9][1024];
    __shared__ float sb9[9];
    int t = threadIdx.x;
    for (int i = t; i < 9 * 1024; i += 256) {
        int c = i / 1024, k = i - c * 1024;
        Wt[c][k] = W[k * 9 + c];
    }
    if (t < 9) sb9[t] = b[t];
    __syncthreads();

    int w = t >> 5, l = t & 31;
    int row = blockIdx.x * 8 + w;
    const float* h = H + (size_t)row * 1024;

    float acc[9];
    #pragma unroll
    for (int c = 0; c < 9; c++) acc[c] = 0.f;
    #pragma unroll 4
    for (int i = 0; i < 32; i++) {
        int k = l + 32 * i;
        float hv = h[k];
        #pragma unroll
        for (int c = 0; c < 9; c++) acc[c] += hv * Wt[c][k];
    }
    #pragma unroll
    for (int o = 16; o; o >>= 1)
        #pragma unroll
        for (int c = 0; c < 9; c++)
            acc[c] += __shfl_xor_sync(0xFFFFFFFFu, acc[c], o);
    if (l == 0) {
        #pragma unroll
        for (int c = 0; c < 9; c++) out[row * 9 + c] = acc[c] + sb9[c];
    }
}

// ===================== launch =====================
extern "C" void kernel_launch(void* const* d_in, const int* in_sizes, int n_in,
                              void* d_out, int out_size)
{
    const float* x   = (const float*)d_in[0];
    const void*  ei  = d_in[1];
    const float* W1  = (const float*)d_in[3];
    const float* a1s = (const float*)d_in[4];
    const float* a1d = (const float*)d_in[5];
    const float* b1  = (const float*)d_in[6];
    const float* W2  = (const float*)d_in[7];
    const float* a2s = (const float*)d_in[8];
    const float* a2d = (const float*)d_in[9];
    const float* b2  = (const float*)d_in[10];
    const float* W3  = (const float*)d_in[11];
    const float* a3s = (const float*)d_in[12];
    const float* a3d = (const float*)d_in[13];
    const float* b3  = (const float*)d_in[14];
    const float* lW1 = (const float*)d_in[15];
    const float* lb1 = (const float*)d_in[16];
    const float* lW2 = (const float*)d_in[17];
    const float* lb2 = (const float*)d_in[18];
    const float* lW3 = (const float*)d_in[19];
    const float* lb3 = (const float*)d_in[20];

    int N   = in_sizes[0];
    int B   = N / NPG;
    int E   = in_sizes[1] / 2;
    int EPG = E / B;

    float *H;
    __nv_bfloat16 *A1, *B1, *A2, *B2;
    cudaGetSymbolAddress((void**)&H, g_H);
    cudaGetSymbolAddress((void**)&A1, g_A1);
    cudaGetSymbolAddress((void**)&B1, g_B1);
    cudaGetSymbolAddress((void**)&A2, g_A2);
    cudaGetSymbolAddress((void**)&B2, g_B2);

    cudaFuncSetAttribute((const void*)k_mma<1, 3>,
        cudaFuncAttributeMaxDynamicSharedMemorySize, SMEM_NB3);
    cudaFuncSetAttribute((const void*)k_mma<0, 4>,
        cudaFuncAttributeMaxDynamicSharedMemorySize, SMEM_NB4);

    k_sniff<<<1, 32>>>((const int*)ei);

    // weight prep
    {
        dim3 blk(32, 8);
        dim3 g1((5000 + 31) / 32, (3280 + 31) / 32);
        k_splitB<<<g1, blk>>>(lW1, B1, 3280, 5000, K1TT);
        dim3 g2((1024 + 31) / 32, (5000 + 31) / 32);
        k_splitB<<<g2, blk>>>(lW2, B2, 5000, 1024, K2TT);
    }

    // fused: res0 + 3 GAT layers + split-bf16 A1 row
    k_fgat<<<B, 256>>>(x, ei, E, EPG,
                       W1, a1s, a1d, b1, W2, a2s, a2d, b2, W3, a3s, a3d, b3,
                       A1);

    // GEMM1 (N-tile 96) -> A2 (split bf16)
    {
        dim3 grid(N1PAD / 96, BGR / 128);    // 54 x 32
        k_mma<1, 3><<<grid, 128, SMEM_NB3>>>(A1, B1, lb1, (float*)nullptr,
                                             A2, K2TT, K2SEC,
                                             K1TT, K1TT / 64, 5000);
    }

    // GEMM2 (N-tile 128) -> H
    {
        dim3 grid(1024 / 128, BGR / 128);    // 8 x 32
        k_mma<0, 4><<<grid, 128, SMEM_NB4>>>(A2, B2, lb2, H,
                                             (__nv_bfloat16*)nullptr, 0, 0,
                                             K2TT, K2TT / 64, 1024);
    }

    k_lin3<<<BGR / 8, 256>>>(H, lW3, lb3, (float*)d_out);
}

// round 16
// speedup vs baseline: 1.0318x; 1.0318x over previous
#include <cuda_runtime.h>
#include <cuda_bf16.h>
#include <stdint.h>

#define NPG  39
#define FDIM 3280
#define BGR  4096
#define MAXE (NPG * 9)

// Frow offsets (concat order)
#define OFF_RES1 39
#define OFF_RES2 351
#define OFF_RES3 2847
#define OFF_OUT0 3198
#define OFF_OUT1 3199
#define OFF_OUT2 3207
#define OFF_OUT3 3271

// GEMM1: K=3280, K'=9840 -> 9856 (154*64). N-tile 128 -> N1PAD 5120.
// GEMM2: K=5000, K'=15000 -> 15040 (235*64). N-tile 128.
#define K1SEC 3280
#define K1TT  9856
#define K2SEC 5000
#define K2TT  15040
#define N1PAD 5120

__device__ float g_H[(size_t)BGR * 1024];
__device__ __align__(128) __nv_bfloat16 g_A1[(size_t)BGR * K1TT];
__device__ __align__(128) __nv_bfloat16 g_B1[(size_t)N1PAD * K1TT];
__device__ __align__(128) __nv_bfloat16 g_A2[(size_t)BGR * K2TT];
__device__ __align__(128) __nv_bfloat16 g_B2[(size_t)1024 * K2TT];
__device__ int g_is64;

__device__ __forceinline__ uint32_t smem_u32(const void* p) {
    uint32_t a;
    asm("{ .reg .u64 t; cvta.to.shared.u64 t, %1; cvt.u32.u64 %0, t; }"
        : "=r"(a) : "l"(p));
    return a;
}

__global__ void k_sniff(const int* __restrict__ ei) {
    if (threadIdx.x == 0) g_is64 = (ei[8] == 0) ? 1 : 0;
}

// ===================== fused GAT layer (device) =====================
template <int FIN, int FOUT>
__device__ __forceinline__ void gat_layer(
    int t,
    const float* __restrict__ xin,
    const float* __restrict__ W, const float* __restrict__ as_,
    const float* __restrict__ ad_, const float* __restrict__ bias,
    float* __restrict__ out, float* __restrict__ maxout,
    float* __restrict__ sh, float* __restrict__ sW,
    float* __restrict__ sas, float* __restrict__ sad, float* __restrict__ sb,
    float* __restrict__ ss, float* __restrict__ sd, float* __restrict__ sden,
    float* __restrict__ sew, const short* __restrict__ sse,
    const int* __restrict__ cnt)
{
    for (int i = t; i < FIN * FOUT; i += 256) sW[i] = W[i];
    if (t < FOUT) { sas[t] = as_[t]; sad[t] = ad_[t]; sb[t] = bias[t]; }
    __syncthreads();

    if (FOUT % 4 == 0) {
        constexpr int F4 = FOUT / 4;
        for (int idx = t; idx < NPG * F4; idx += 256) {
            int i = idx / F4, f4 = idx - i * F4;
            float4 a = make_float4(0.f, 0.f, 0.f, 0.f);
            #pragma unroll
            for (int k = 0; k < FIN; k++) {
                float xv = xin[i * FIN + k];
                float4 wv = *(const float4*)&sW[k * FOUT + f4 * 4];
                a.x += xv * wv.x; a.y += xv * wv.y;
                a.z += xv * wv.z; a.w += xv * wv.w;
            }
            *(float4*)&sh[i * FOUT + f4 * 4] = a;
        }
    } else {
        for (int idx = t; idx < NPG * FOUT; idx += 256) {
            int i = idx / FOUT, f = idx - i * FOUT;
            float a = 0.f;
            #pragma unroll 8
            for (int k = 0; k < FIN; k++) a += xin[i * FIN + k] * sW[k * FOUT + f];
            sh[idx] = a;
        }
    }
    __syncthreads();

    for (int i = t; i < NPG; i += 256) {
        float a = 0.f, b = 0.f;
        #pragma unroll
        for (int f = 0; f < FOUT; f++) {
            a += sh[i * FOUT + f] * sas[f];
            b += sh[i * FOUT + f] * sad[f];
        }
        ss[i] = a; sd[i] = b;
    }
    __syncthreads();

    // segment softmax in sorted domain
    for (int i = t; i < NPG; i += 256) {
        int e0 = cnt[i], e1 = cnt[i + 1];
        float di = sd[i];
        float mx = -1e30f;
        for (int p = e0; p < e1; p++) {
            float sc = ss[sse[p]] + di;
            sc = sc > 0.f ? sc : 0.2f * sc;
            sew[p] = sc;
            mx = fmaxf(mx, sc);
        }
        float s = 0.f;
        for (int p = e0; p < e1; p++) {
            float w = __expf(sew[p] - mx);
            sew[p] = w;
            s += w;
        }
        sden[i] = s;
    }
    __syncthreads();

    if (FOUT % 4 == 0) {
        constexpr int F4 = FOUT / 4;
        for (int idx = t; idx < NPG * F4; idx += 256) {
            int i = idx / F4, f4 = idx - i * F4;
            float4 a = make_float4(0.f, 0.f, 0.f, 0.f);
            int e0 = cnt[i], e1 = cnt[i + 1];
            for (int p = e0; p < e1; p++) {
                float w = sew[p];
                float4 hv = *(const float4*)&sh[(int)sse[p] * FOUT + f4 * 4];
                a.x += w * hv.x; a.y += w * hv.y;
                a.z += w * hv.z; a.w += w * hv.w;
            }
            float inv = 1.f / (sden[i] + 1e-16f);
            int base = i * FOUT + f4 * 4;
            out[base + 0] = fmaxf(a.x * inv + sb[f4 * 4 + 0], 0.f);
            out[base + 1] = fmaxf(a.y * inv + sb[f4 * 4 + 1], 0.f);
            out[base + 2] = fmaxf(a.z * inv + sb[f4 * 4 + 2], 0.f);
            out[base + 3] = fmaxf(a.w * inv + sb[f4 * 4 + 3], 0.f);
        }
    } else {
        for (int idx = t; idx < NPG * FOUT; idx += 256) {
            int i = idx / FOUT, f = idx - i * FOUT;
            float a = 0.f;
            int e0 = cnt[i], e1 = cnt[i + 1];
            for (int p = e0; p < e1; p++)
                a += sew[p] * sh[(int)sse[p] * FOUT + f];
            out[idx] = fmaxf(a / (sden[i] + 1e-16f) + sb[f], 0.f);
        }
    }
    __syncthreads();

    for (int f = t; f < FOUT; f += 256) {
        float mv = out[f];
        for (int i = 1; i < NPG; i++) mv = fmaxf(mv, out[i * FOUT + f]);
        maxout[f] = mv;
    }
    __syncthreads();
}

// ===================== fused GAT kernel (4 CTAs/SM) =====================
__global__ __launch_bounds__(256, 4) void k_fgat(
    const float* __restrict__ x, const void* __restrict__ edges,
    int E, int EPG,
    const float* __restrict__ W1, const float* __restrict__ a1s,
    const float* __restrict__ a1d, const float* __restrict__ b1,
    const float* __restrict__ W2, const float* __restrict__ a2s,
    const float* __restrict__ a2d, const float* __restrict__ b2,
    const float* __restrict__ W3, const float* __restrict__ a3s,
    const float* __restrict__ a3d, const float* __restrict__ b3,
    __nv_bfloat16* __restrict__ A1)
{
    __shared__ __align__(16) float Frow[FDIM];
    __shared__ __align__(16) float sh[NPG * 64];
    __shared__ __align__(16) float sW[64 * 9];
    __shared__ float sas[64], sad[64], sb[64];
    __shared__ float ss[NPG], sd[NPG], sden[NPG];
    __shared__ float sew[MAXE];
    __shared__ short elsA[MAXE], eldA[MAXE], sse[MAXE];
    __shared__ int cnt[NPG + 1], off[NPG];

    int g = blockIdx.x;
    int t = threadIdx.x;
    int nE = EPG + NPG;

    if (t < NPG) Frow[t] = x[g * NPG + t];
    if (t < NPG + 1) cnt[t] = 0;
    __syncthreads();

    bool is64 = (g_is64 != 0);
    long long node0 = (long long)g * NPG;
    for (int e = t; e < nE; e += 256) {
        int ls, ld;
        if (e < EPG) {
            long long ge = (long long)g * EPG + e;
            long long sv, dv;
            if (is64) {
                const long long* p = (const long long*)edges;
                sv = p[ge]; dv = p[ge + E];
            } else {
                const int* p = (const int*)edges;
                sv = p[ge]; dv = p[ge + E];
            }
            ls = (int)(sv - node0);
            ld = (int)(dv - node0);
        } else {
            ls = ld = e - EPG;
        }
        elsA[e] = (short)ls; eldA[e] = (short)ld;
        atomicAdd(&cnt[ld], 1);
    }
    __syncthreads();

    if (t == 0) {
        int s = 0;
        for (int i = 0; i < NPG; i++) {
            int c = cnt[i];
            cnt[i] = s; off[i] = s;
            s += c;
        }
        cnt[NPG] = s;
    }
    __syncthreads();

    for (int e = t; e < nE; e += 256) {
        int pos = atomicAdd(&off[eldA[e]], 1);
        sse[pos] = elsA[e];
    }
    if (t == 32) {
        float mv = Frow[0];
        for (int i = 1; i < NPG; i++) mv = fmaxf(mv, Frow[i]);
        Frow[OFF_OUT0] = mv;
    }
    __syncthreads();

    gat_layer<1, 8>(t, &Frow[0], W1, a1s, a1d, b1,
                    &Frow[OFF_RES1], &Frow[OFF_OUT1],
                    sh, sW, sas, sad, sb, ss, sd, sden, sew, sse, cnt);
    gat_layer<8, 64>(t, &Frow[OFF_RES1], W2, a2s, a2d, b2,
                     &Frow[OFF_RES2], &Frow[OFF_OUT2],
                     sh, sW, sas, sad, sb, ss, sd, sden, sew, sse, cnt);
    gat_layer<64, 9>(t, &Frow[OFF_RES2], W3, a3s, a3d, b3,
                     &Frow[OFF_RES3], &Frow[OFF_OUT3],
                     sh, sW, sas, sad, sb, ss, sd, sden, sew, sse, cnt);

    __nv_bfloat16* row = A1 + (size_t)g * K1TT;
    for (int k = t; k < FDIM; k += 256) {
        float v = Frow[k];
        __nv_bfloat16 hi = __float2bfloat16(v);
        __nv_bfloat16 lo = __float2bfloat16(v - __bfloat162float(hi));
        row[k] = hi;
        row[K1SEC + k] = hi;
        row[2 * K1SEC + k] = lo;
    }
}

// ===================== weight split ([hi | lo | hi], stride KtT) ==========
__global__ void k_splitB(const float* __restrict__ W, __nv_bfloat16* __restrict__ Bt,
                         int K, int N, int KtT)
{
    __shared__ float tile[32][33];
    int kb = blockIdx.y * 32, nb = blockIdx.x * 32;
    int tx = threadIdx.x, ty = threadIdx.y;
    for (int r = ty; r < 32; r += 8) {
        int k = kb + r, n = nb + tx;
        tile[r][tx] = (k < K && n < N) ? W[(size_t)k * N + n] : 0.f;
    }
    __syncthreads();
    for (int r = ty; r < 32; r += 8) {
        int n = nb + r, k = kb + tx;
        if (n < N && k < K) {
            float v = tile[tx][r];
            __nv_bfloat16 hi = __float2bfloat16(v);
            __nv_bfloat16 lo = __float2bfloat16(v - __bfloat162float(hi));
            __nv_bfloat16* row = Bt + (size_t)n * KtT;
            row[k] = hi;
            row[K + k] = lo;
            row[2 * K + k] = hi;
        }
    }
}

// ===================== mma.sync GEMM (R13 config: 128x128, BK=64) ==========
#define ROWB 144
#define A_STG (128 * ROWB)
#define B_STG (128 * ROWB)
#define STG   (A_STG + B_STG)
#define GEMM_SMEM (3 * STG)

__device__ __forceinline__ void ldm4(uint32_t* r, uint32_t addr) {
    asm volatile("ldmatrix.sync.aligned.m8n8.x4.shared.b16 {%0,%1,%2,%3}, [%4];"
        : "=r"(r[0]), "=r"(r[1]), "=r"(r[2]), "=r"(r[3]) : "r"(addr));
}
__device__ __forceinline__ void mma16816(float* c, const uint32_t* a,
                                         uint32_t b0, uint32_t b1) {
    asm volatile("mma.sync.aligned.m16n8k16.row.col.f32.bf16.bf16.f32 "
        "{%0,%1,%2,%3}, {%4,%5,%6,%7}, {%8,%9}, {%0,%1,%2,%3};"
        : "+f"(c[0]), "+f"(c[1]), "+f"(c[2]), "+f"(c[3])
        : "r"(a[0]), "r"(a[1]), "r"(a[2]), "r"(a[3]), "r"(b0), "r"(b1));
}

__device__ __forceinline__ void wsplit2(__nv_bfloat16* base, int r, int KsT,
                                        int KSec, int col, float v0, float v1) {
    __nv_bfloat16 h0 = __float2bfloat16(v0);
    __nv_bfloat16 h1 = __float2bfloat16(v1);
    __nv_bfloat162 lo2 = __floats2bfloat162_rn(v0 - __bfloat162float(h0),
                                               v1 - __bfloat162float(h1));
    uint32_t hp; { __nv_bfloat162 hh; hh.x = h0; hh.y = h1; hp = *(uint32_t*)&hh; }
    uint32_t lp = *(uint32_t*)&lo2;
    __nv_bfloat16* row = base + (size_t)r * KsT;
    *(uint32_t*)(row + col) = hp;
    *(uint32_t*)(row + KSec + col) = hp;
    *(uint32_t*)(row + 2 * KSec + col) = lp;
}

template <int EPI>
__global__ __launch_bounds__(128, 2) void k_mma(
    const __nv_bfloat16* __restrict__ A, const __nv_bfloat16* __restrict__ B,
    const float* __restrict__ bias, float* __restrict__ C,
    __nv_bfloat16* __restrict__ Csp, int KsT, int KSec,
    int Kt, int steps, int Nreal)
{
    extern __shared__ char smem[];
    uint32_t sb = smem_u32(smem);
    int tid = threadIdx.x;
    int lane = tid & 31, wid = tid >> 5;
    int wm = wid & 1, wn = wid >> 1;
    int bm = blockIdx.y * 128, bn = blockIdx.x * 128;

    const char* Abase = (const char*)A + (size_t)bm * Kt * 2;
    const char* Bbase = (const char*)B + (size_t)bn * Kt * 2;
    size_t gsA = (size_t)Kt * 2;

    auto load_stage = [&](int s, int slot) {
        size_t kb = (size_t)s * 128;
        uint32_t base = sb + slot * STG;
        #pragma unroll
        for (int i = 0; i < 8; i++) {
            int c = tid + i * 128;
            int row = c >> 3, kc = c & 7;
            uint32_t dst = base + row * ROWB + kc * 16;
            const char* src = Abase + (size_t)row * gsA + kb + kc * 16;
            asm volatile("cp.async.cg.shared.global [%0], [%1], 16;"
                         :: "r"(dst), "l"(src));
        }
        #pragma unroll
        for (int i = 0; i < 8; i++) {
            int c = tid + i * 128;
            int row = c >> 3, kc = c & 7;
            uint32_t dst = base + A_STG + row * ROWB + kc * 16;
            const char* src = Bbase + (size_t)row * gsA + kb + kc * 16;
            asm volatile("cp.async.cg.shared.global [%0], [%1], 16;"
                         :: "r"(dst), "l"(src));
        }
    };

    float acc[4][8][4];
    #pragma unroll
    for (int i = 0; i < 4; i++)
        #pragma unroll
        for (int j = 0; j < 8; j++)
            #pragma unroll
            for (int q = 0; q < 4; q++) acc[i][j][q] = 0.f;

    load_stage(0, 0);
    asm volatile("cp.async.commit_group;" ::: "memory");
    load_stage(1, 1);
    asm volatile("cp.async.commit_group;" ::: "memory");

    int lr = lane & 15;
    int lc = (lane >> 4) * 16;

    for (int j = 0; j < steps; j++) {
        asm volatile("cp.async.wait_group 1;" ::: "memory");
        __syncthreads();

        if (j + 2 < steps) load_stage(j + 2, (j + 2) % 3);
        asm volatile("cp.async.commit_group;" ::: "memory");

        uint32_t sA = sb + (j % 3) * STG;
        uint32_t sB = sA + A_STG;
        uint32_t aA = sA + (wm * 64 + lr) * ROWB + lc;
        uint32_t aB = sB + (wn * 64 + lr) * ROWB + lc;

        #pragma unroll
        for (int ks = 0; ks < 4; ks++) {
            uint32_t a[4][4], b[4][4];
            #pragma unroll
            for (int mi = 0; mi < 4; mi++)
                ldm4(a[mi], aA + mi * 16 * ROWB + ks * 32);
            #pragma unroll
            for (int ng = 0; ng < 4; ng++)
                ldm4(b[ng], aB + ng * 16 * ROWB + ks * 32);
            #pragma unroll
            for (int mi = 0; mi < 4; mi++)
                #pragma unroll
                for (int ng = 0; ng < 4; ng++) {
                    mma16816(acc[mi][2 * ng],     a[mi], b[ng][0], b[ng][2]);
                    mma16816(acc[mi][2 * ng + 1], a[mi], b[ng][1], b[ng][3]);
                }
        }
    }

    int r0base = bm + wm * 64 + (lane >> 2);
    int c0base = bn + wn * 64 + (lane & 3) * 2;
    #pragma unroll
    for (int mi = 0; mi < 4; mi++) {
        #pragma unroll
        for (int ni = 0; ni < 8; ni++) {
            int col = c0base + ni * 8;
            if (EPI == 1 && col >= Nreal) continue;  // col even, Nreal even
            float bv0 = __ldg(&bias[col]);
            float bv1 = __ldg(&bias[col + 1]);
            int r0 = r0base + mi * 16;
            int r1 = r0 + 8;
            float v0 = fmaxf(acc[mi][ni][0] + bv0, 0.f);
            float v1 = fmaxf(acc[mi][ni][1] + bv1, 0.f);
            float v2 = fmaxf(acc[mi][ni][2] + bv0, 0.f);
            float v3 = fmaxf(acc[mi][ni][3] + bv1, 0.f);
            if (EPI == 0) {
                *(float2*)(C + (size_t)r0 * Nreal + col) = make_float2(v0, v1);
                *(float2*)(C + (size_t)r1 * Nreal + col) = make_float2(v2, v3);
            } else {
                wsplit2(Csp, r0, KsT, KSec, col, v0, v1);
                wsplit2(Csp, r1, KsT, KSec, col, v2, v3);
            }
        }
    }
}

// ===================== final skinny layer =====================
__global__ __launch_bounds__(256) void k_lin3(
    const float* __restrict__ H, const float* __restrict__ W,
    const float* __restrict__ b, float* __restrict__ out)
{
    __shared__ float Wt[9][1024];
    __shared__ float sb9[9];
    int t = threadIdx.x;
    for (int i = t; i < 9 * 1024; i += 256) {
        int c = i / 1024, k = i - c * 1024;
        Wt[c][k] = W[k * 9 + c];
    }
    if (t < 9) sb9[t] = b[t];
    __syncthreads();

    int w = t >> 5, l = t & 31;
    int row = blockIdx.x * 8 + w;
    const float* h = H + (size_t)row * 1024;

    float acc[9];
    #pragma unroll
    for (int c = 0; c < 9; c++) acc[c] = 0.f;
    #pragma unroll 4
    for (int i = 0; i < 32; i++) {
        int k = l + 32 * i;
        float hv = h[k];
        #pragma unroll
        for (int c = 0; c < 9; c++) acc[c] += hv * Wt[c][k];
    }
    #pragma unroll
    for (int o = 16; o; o >>= 1)
        #pragma unroll
        for (int c = 0; c < 9; c++)
            acc[c] += __shfl_xor_sync(0xFFFFFFFFu, acc[c], o);
    if (l == 0) {
        #pragma unroll
        for (int c = 0; c < 9; c++) out[row * 9 + c] = acc[c] + sb9[c];
    }
}

// ===================== launch =====================
extern "C" void kernel_launch(void* const* d_in, const int* in_sizes, int n_in,
                              void* d_out, int out_size)
{
    const float* x   = (const float*)d_in[0];
    const void*  ei  = d_in[1];
    const float* W1  = (const float*)d_in[3];
    const float* a1s = (const float*)d_in[4];
    const float* a1d = (const float*)d_in[5];
    const float* b1  = (const float*)d_in[6];
    const float* W2  = (const float*)d_in[7];
    const float* a2s = (const float*)d_in[8];
    const float* a2d = (const float*)d_in[9];
    const float* b2  = (const float*)d_in[10];
    const float* W3  = (const float*)d_in[11];
    const float* a3s = (const float*)d_in[12];
    const float* a3d = (const float*)d_in[13];
    const float* b3  = (const float*)d_in[14];
    const float* lW1 = (const float*)d_in[15];
    const float* lb1 = (const float*)d_in[16];
    const float* lW2 = (const float*)d_in[17];
    const float* lb2 = (const float*)d_in[18];
    const float* lW3 = (const float*)d_in[19];
    const float* lb3 = (const float*)d_in[20];

    int N   = in_sizes[0];
    int B   = N / NPG;
    int E   = in_sizes[1] / 2;
    int EPG = E / B;

    float *H;
    __nv_bfloat16 *A1, *B1, *A2, *B2;
    cudaGetSymbolAddress((void**)&H, g_H);
    cudaGetSymbolAddress((void**)&A1, g_A1);
    cudaGetSymbolAddress((void**)&B1, g_B1);
    cudaGetSymbolAddress((void**)&A2, g_A2);
    cudaGetSymbolAddress((void**)&B2, g_B2);

    cudaFuncSetAttribute(k_mma<0>,
        cudaFuncAttributeMaxDynamicSharedMemorySize, GEMM_SMEM);
    cudaFuncSetAttribute(k_mma<1>,
        cudaFuncAttributeMaxDynamicSharedMemorySize, GEMM_SMEM);

    k_sniff<<<1, 32>>>((const int*)ei);

    // weight prep
    {
        dim3 blk(32, 8);
        dim3 g1((5000 + 31) / 32, (3280 + 31) / 32);
        k_splitB<<<g1, blk>>>(lW1, B1, 3280, 5000, K1TT);
        dim3 g2((1024 + 31) / 32, (5000 + 31) / 32);
        k_splitB<<<g2, blk>>>(lW2, B2, 5000, 1024, K2TT);
    }

    // fused: res0 + 3 GAT layers + split-bf16 A1 row
    k_fgat<<<B, 256>>>(x, ei, E, EPG,
                       W1, a1s, a1d, b1, W2, a2s, a2d, b2, W3, a3s, a3d, b3,
                       A1);

    // GEMM1 (N-tile 128) -> A2 (split bf16)
    {
        dim3 grid(N1PAD / 128, BGR / 128);   // 40 x 32
        k_mma<1><<<grid, 128, GEMM_SMEM>>>(A1, B1, lb1, (float*)nullptr,
                                           A2, K2TT, K2SEC,
                                           K1TT, K1TT / 64, 5000);
    }

    // GEMM2 (N-tile 128) -> H
    {
        dim3 grid(1024 / 128, BGR / 128);    // 8 x 32
        k_mma<0><<<grid, 128, GEMM_SMEM>>>(A2, B2, lb2, H,
                                           (__nv_bfloat16*)nullptr, 0, 0,
                                           K2TT, K2TT / 64, 1024);
    }

    k_lin3<<<BGR / 8, 256>>>(H, lW3, lb3, (float*)d_out);
}